// round 16
// baseline (speedup 1.0000x reference)
#include <cuda_runtime.h>
#include <cstdint>
#include <cstddef>

// Problem shape (fixed for this registry entry)
#define B_ROWS 4096
#define T_LEN  8192
#define K_WIN  5

// ---- tiling: WTILE=128 (measured-best), single in-place ring, 4 slots ----
#define ROWS   32                 // rows per block (one lane per row in LIF/combiner warps)
#define WTILE  128                // timesteps per tile
#define SLOTS  4                  // ring depth (x overwritten by spike masks in place)
#define NTILES (T_LEN / WTILE)    // 64
#define GPR    (WTILE / 4)        // 32 float4 per row-tile
#define RSTR   33                 // padded row stride (f4): conflict-free LDS.128

#define X_F4   (SLOTS * 3 * ROWS * RSTR)    // 12672 f4 = 202.7 KB
#define SMEM_BYTES (X_F4 * 16)

// Normalization speculation: sal values are exact integers in {0,1,2,3}; rows
// almost surely reach max=3 (verified R9-R15: fixup is a universal fast-path exit).
#define INV3 (1.0f / 3.000001f)

#define PAR4(i) ((unsigned)((((unsigned)(i)) >> 2) & 1u))

// ---------------- mbarrier helpers ----------------
__device__ __forceinline__ void mbar_init(unsigned addr, unsigned count) {
    asm volatile("mbarrier.init.shared.b64 [%0], %1;" :: "r"(addr), "r"(count) : "memory");
}
__device__ __forceinline__ void mbar_arrive(unsigned addr) {
    asm volatile("mbarrier.arrive.shared.b64 _, [%0];" :: "r"(addr) : "memory");
}
__device__ __forceinline__ void mbar_wait(unsigned addr, unsigned parity) {
    unsigned done;
    asm volatile("{\n\t.reg .pred p;\n\t"
                 "mbarrier.try_wait.parity.acquire.cta.shared::cta.b64 p, [%1], %2;\n\t"
                 "selp.b32 %0, 1, 0, p;\n\t}"
                 : "=r"(done) : "r"(addr), "r"(parity) : "memory");
    if (!done) {
        asm volatile("{\n\t.reg .pred P1;\n\t"
                     "WL_%=:\n\t"
                     "mbarrier.try_wait.parity.acquire.cta.shared::cta.b64 P1, [%0], %1, 0x989680;\n\t"
                     "@P1 bra.uni WD_%=;\n\t"
                     "bra.uni WL_%=;\n\t"
                     "WD_%=:\n\t}"
                     :: "r"(addr), "r"(parity) : "memory");
    }
}
__device__ __forceinline__ void cp_async16(unsigned smem_addr, const void* gptr) {
    asm volatile("cp.async.cg.shared.global [%0], [%1], 16;" :: "r"(smem_addr), "l"(gptr));
}
__device__ __forceinline__ void cp_async_arrive_noinc(unsigned mbar_addr) {
    asm volatile("cp.async.mbarrier.arrive.noinc.shared.b64 [%0];" :: "r"(mbar_addr) : "memory");
}

// ---------------- top-5 streaming insert (strict > preserves lowest-index ties) ----
__device__ __forceinline__ void top5_insert(float s, int t, float tv[5], int ti[5]) {
    if (s > tv[4]) {
        if (s > tv[0]) {
            tv[4]=tv[3]; ti[4]=ti[3]; tv[3]=tv[2]; ti[3]=ti[2];
            tv[2]=tv[1]; ti[2]=ti[1]; tv[1]=tv[0]; ti[1]=ti[0];
            tv[0]=s; ti[0]=t;
        } else if (s > tv[1]) {
            tv[4]=tv[3]; ti[4]=ti[3]; tv[3]=tv[2]; ti[3]=ti[2];
            tv[2]=tv[1]; ti[2]=ti[1]; tv[1]=s; ti[1]=t;
        } else if (s > tv[2]) {
            tv[4]=tv[3]; ti[4]=ti[3]; tv[3]=tv[2]; ti[3]=ti[2];
            tv[2]=s; ti[2]=t;
        } else if (s > tv[3]) {
            tv[4]=tv[3]; ti[4]=ti[3]; tv[3]=s; ti[3]=t;
        } else {
            tv[4]=s; ti[4]=t;
        }
    }
}

// 2-step speculative LIF: consumes (x0,x1); emits masks (m0,m1); advances v two steps.
// Bitwise identical to the sequential recurrence:
//   a0 = fmaf(d,v,x0); s0=(a0>=1); v1=a0-s0 (Sterbenz-exact)
//   a1 = fmaf(d,v1,x1) = s0 ? D1 : D0 ; s1 = s0?q1:q0 ; v2 = a1 - s1
// Both successor candidates are computed off-chain; the critical path is
// a0(4) -> {p0(17) | q1(25) | D1m(16)} -> inner FSEL(29) -> outer FSEL(33)
// = 16.5 cyc/step vs 21 for the sequential FSETP->FSEL form.
__device__ __forceinline__ void lif2(float x0, float x1, float d, float& v,
                                     float& m0, float& m1) {
    float a0  = fmaf(d, v, x0);
    float u0  = a0 - 1.0f;
    bool  p0  = (a0 >= 1.0f);
    float D0  = fmaf(d, a0, x1);   // a1 candidate: no spike at step t
    float D1  = fmaf(d, u0, x1);   // a1 candidate: spike at step t
    float D0m = D0 - 1.0f;
    float D1m = D1 - 1.0f;
    bool  q0  = (D0 >= 1.0f);
    bool  q1  = (D1 >= 1.0f);
    m0 = p0 ? 1.0f : 0.0f;
    m1 = p0 ? (q1 ? 1.0f : 0.0f) : (q0 ? 1.0f : 0.0f);
    v  = p0 ? (q1 ? D1m : D1) : (q0 ? D0m : D0);
}

// =====================================================================================
// Single fused kernel — 8 warps, single 4-slot in-place ring (R15 structure frozen):
//   warp 0 (SMSP0): filler rows 0-15      warp 4 (SMSP0): filler rows 16-31
//   warp 1 (SMSP1): combiner
//   warp 2 (SMSP2): drainer A (rows 0-15) warp 3 (SMSP3): drainer B (rows 16-31)
//   warp 5 (SMSP1): LIF ch0   warp 6 (SMSP2): LIF ch1   warp 7 (SMSP3): LIF ch2
// Ring protocol per slot s:
//   filler: wait sdone[s] (i>=4) -> cp.async x -> arrive full[s]
//   LIF:    wait full[s]         -> read x / overwrite with masks -> arrive cdone[s]
//   comb+drainers: wait cdone[s] -> read masks -> arrive sdone[s]
// Epilogue: fused fixup via named barrier 7 (96 threads; measure-zero miss path).
// =====================================================================================
extern "C" __global__ void __launch_bounds__(256, 1)
msa_pass1(const float* __restrict__ amp, const float* __restrict__ pitch,
          const float* __restrict__ bnd, const float* __restrict__ decay,
          const float* __restrict__ weights, float* __restrict__ out)
{
    extern __shared__ float4 smem[];
    float4* smx = smem;            // 4-slot ring: x tiles, overwritten by spike masks
    float*  sfix = reinterpret_cast<float*>(smx);   // 32 floats, safe after all drains
    __shared__ __align__(8) unsigned long long s_mb[12];
    unsigned mb = (unsigned)__cvta_generic_to_shared(s_mb);
    // full[s]: s*8 ; cdone[s]: (4+s)*8 ; sdone[s]: (8+s)*8

    const int tid  = threadIdx.x;
    const int lane = tid & 31;
    const int warp = tid >> 5;
    const int b0   = blockIdx.x * ROWS;

    if (tid == 0) {
        #pragma unroll
        for (int s = 0; s < SLOTS; ++s) {
            mbar_init(mb + (0 + s) * 8, 64);   // full  (2 filler warps x 32)
            mbar_init(mb + (4 + s) * 8, 96);   // cdone (3 LIF warps)
            mbar_init(mb + (8 + s) * 8, 96);   // sdone (combiner + 2 drainers)
        }
        asm volatile("fence.proxy.async.shared::cta;" ::: "memory");
    }
    __syncthreads();

    float* out_sal = out + B_ROWS;

    if (warp == 0 || warp == 4) {
        // ---------------- fillers: lane = 16B chunk (0..31), each covers 16 rows ----
        const int cc = lane;
        const int rbase = (warp == 0) ? 0 : 16;
        for (int i = 0; i < NTILES; ++i) {
            const int s = i & 3;
            if (i >= SLOTS)
                mbar_wait(mb + (8 + s) * 8, PAR4(i - SLOTS));   // slot fully consumed
            #pragma unroll
            for (int c = 0; c < 3; ++c) {
                const float* src = (c == 0) ? amp : (c == 1) ? pitch : bnd;
                float4* dst = smx + (size_t)(s * 3 + c) * ROWS * RSTR;
                #pragma unroll 8
                for (int q = 0; q < 16; ++q) {
                    const int r = rbase + q;
                    unsigned sa = (unsigned)__cvta_generic_to_shared(dst + r * RSTR + cc);
                    cp_async16(sa, src + (size_t)(b0 + r) * T_LEN
                                   + (size_t)i * WTILE + cc * 4);
                }
            }
            cp_async_arrive_noinc(mb + (0 + s) * 8);            // full
        }
    } else if (warp >= 5) {
        // ------- LIF warp, channel c = warp-5: lane = row; in-place mask write -------
        const int c = warp - 5;
        const int r = lane;
        const float d = __ldg(&decay[c]);
        float v = 0.0f;

        for (int i = 0; i < NTILES; ++i) {
            const int s = i & 3;
            mbar_wait(mb + (0 + s) * 8, PAR4(i));               // x ready (ONLY wait)

            float4* X = smx + ((size_t)(s * 3 + c) * ROWS + r) * RSTR;

            float4 nxt = X[0];
            #pragma unroll 8
            for (int g = 0; g < GPR; ++g) {
                const float4 x = nxt;
                if (g + 1 < GPR) nxt = X[g + 1];   // prefetch before overwrite of X[g]
                float4 m;
                lif2(x.x, x.y, d, v, m.x, m.y);    // steps 4g, 4g+1
                lif2(x.z, x.w, d, v, m.z, m.w);    // steps 4g+2, 4g+3
                X[g] = m;                          // in-place: x slot becomes mask slot
            }
            mbar_arrive(mb + (4 + s) * 8);                      // cdone
        }
    } else if (warp == 1) {
        // ---------------- combiner: lane = row; max + gated top-5 ----------------
        const int r = lane;
        const float w0 = __ldg(&weights[0]), w1 = __ldg(&weights[1]), w2 = __ldg(&weights[2]);
        float mx = 0.0f;
        float tv[K_WIN] = {-1.0f, -1.0f, -1.0f, -1.0f, -1.0f};
        int   ti[K_WIN] = {0, 0, 0, 0, 0};

        for (int i = 0; i < NTILES; ++i) {
            const int s = i & 3;
            mbar_wait(mb + (4 + s) * 8, PAR4(i));               // masks ready

            const float4* S0 = smx + ((size_t)(s * 3 + 0) * ROWS + r) * RSTR;
            const float4* S1 = smx + ((size_t)(s * 3 + 1) * ROWS + r) * RSTR;
            const float4* S2 = smx + ((size_t)(s * 3 + 2) * ROWS + r) * RSTR;

            float tm = -1.0f;
            #pragma unroll 8
            for (int g = 0; g < GPR; ++g) {
                const float4 m0 = S0[g];
                const float4 m1 = S1[g];
                const float4 m2 = S2[g];
                float4 sv;
                sv.x = fmaf(w2, m2.x, fmaf(w1, m1.x, w0 * m0.x));
                sv.y = fmaf(w2, m2.y, fmaf(w1, m1.y, w0 * m0.y));
                sv.z = fmaf(w2, m2.z, fmaf(w1, m1.z, w0 * m0.z));
                sv.w = fmaf(w2, m2.w, fmaf(w1, m1.w, w0 * m0.w));
                tm = fmaxf(tm, fmaxf(fmaxf(sv.x, sv.y), fmaxf(sv.z, sv.w)));
            }
            mx = fmaxf(mx, tm);

            // Gated rescan: only when this tile beats the current 5th value (rare).
            if (tm > tv[4]) {
                const int tb = i * WTILE;
                for (int g = 0; g < GPR; ++g) {
                    const float4 m0 = S0[g];
                    const float4 m1 = S1[g];
                    const float4 m2 = S2[g];
                    float4 sv;
                    sv.x = fmaf(w2, m2.x, fmaf(w1, m1.x, w0 * m0.x));
                    sv.y = fmaf(w2, m2.y, fmaf(w1, m1.y, w0 * m0.y));
                    sv.z = fmaf(w2, m2.z, fmaf(w1, m1.z, w0 * m0.z));
                    sv.w = fmaf(w2, m2.w, fmaf(w1, m1.w, w0 * m0.w));
                    const int t = tb + g * 4;
                    top5_insert(sv.x, t + 0, tv, ti);
                    top5_insert(sv.y, t + 1, tv, ti);
                    top5_insert(sv.z, t + 2, tv, ti);
                    top5_insert(sv.w, t + 3, tv, ti);
                }
            }
            mbar_arrive(mb + (8 + s) * 8);                      // sdone (1 of 3)
        }

        // ---- row tail: mu, topk_idx; publish fix factor for epilogue ----
        const int b = b0 + r;
        const float inv = 1.0f / (mx + 1e-6f);
        const float fix = (mx == 3.0f) ? 1.0f : (3.000001f * inv);
        sfix[r] = fix;     // ring is dead by now
        const float n0 = tv[0]*inv, n1 = tv[1]*inv, n2 = tv[2]*inv,
                    n3 = tv[3]*inv, n4 = tv[4]*inv;
        const float avg = ((((n0 + n1) + n2) + n3) + n4) / 5.0f;
        out[b] = 0.5f + 2.0f * tanhf(1.8f * avg);
        float* out_idx = out + B_ROWS + (size_t)B_ROWS * T_LEN;
        #pragma unroll
        for (int k = 0; k < K_WIN; ++k)
            out_idx[(size_t)b * K_WIN + k] = (float)ti[k];

        // ---- epilogue: meet drainers, rescale own row if needed (measure-zero path) ----
        asm volatile("bar.sync 7, 96;" ::: "memory");
        const float f = sfix[r];
        if (f != 1.0f) {
            float4* row4 = reinterpret_cast<float4*>(out_sal + (size_t)b * T_LEN);
            for (int it = 0; it < T_LEN / 8; ++it) {       // first half of row
                float4 vv = row4[it];
                vv.x *= f; vv.y *= f; vv.z *= f; vv.w *= f;
                row4[it] = vv;
            }
        }
    } else {
        // -------- drainers (warps 2,3): lane = 16B chunk; 16 rows each --------
        const int cc = lane;
        const int rbase = (warp == 2) ? 0 : 16;
        const float w0 = __ldg(&weights[0]), w1 = __ldg(&weights[1]), w2 = __ldg(&weights[2]);
        for (int j = 0; j < NTILES; ++j) {
            const int s = j & 3;
            mbar_wait(mb + (4 + s) * 8, PAR4(j));               // masks ready
            const float4* P0 = smx + (size_t)(s * 3 + 0) * ROWS * RSTR;
            const float4* P1 = smx + (size_t)(s * 3 + 1) * ROWS * RSTR;
            const float4* P2 = smx + (size_t)(s * 3 + 2) * ROWS * RSTR;
            #pragma unroll 4
            for (int q = 0; q < 16; ++q) {
                const int r = rbase + q;
                const float4 m0 = P0[r * RSTR + cc];
                const float4 m1 = P1[r * RSTR + cc];
                const float4 m2 = P2[r * RSTR + cc];
                float4 sv;
                sv.x = fmaf(w2, m2.x, fmaf(w1, m1.x, w0 * m0.x)) * INV3;
                sv.y = fmaf(w2, m2.y, fmaf(w1, m1.y, w0 * m0.y)) * INV3;
                sv.z = fmaf(w2, m2.z, fmaf(w1, m1.z, w0 * m0.z)) * INV3;
                sv.w = fmaf(w2, m2.w, fmaf(w1, m1.w, w0 * m0.w)) * INV3;
                __stcs(reinterpret_cast<float4*>(out_sal + (size_t)(b0 + r) * T_LEN
                                                 + (size_t)j * WTILE + cc * 4), sv);
            }
            mbar_arrive(mb + (8 + s) * 8);                      // sdone (2,3 of 3)
        }

        // ---- epilogue: meet combiner; warp 2 rescales second half of rows if needed ----
        asm volatile("bar.sync 7, 96;" ::: "memory");
        if (warp == 2) {
            const int r = lane;
            const float f = sfix[r];
            if (f != 1.0f) {
                float4* row4 = reinterpret_cast<float4*>(out_sal + (size_t)(b0 + r) * T_LEN);
                for (int it = T_LEN / 8; it < T_LEN / 4; ++it) {   // second half of row
                    float4 vv = row4[it];
                    vv.x *= f; vv.y *= f; vv.z *= f; vv.w *= f;
                    row4[it] = vv;
                }
            }
        }
    }
}

extern "C" void kernel_launch(void* const* d_in, const int* in_sizes, int n_in,
                              void* d_out, int out_size) {
    (void)in_sizes; (void)n_in; (void)out_size;
    const float* amp     = (const float*)d_in[0];
    const float* pitch   = (const float*)d_in[1];
    const float* bnd     = (const float*)d_in[2];
    const float* decay   = (const float*)d_in[3];
    const float* weights = (const float*)d_in[4];
    float* out = (float*)d_out;

    cudaFuncSetAttribute(msa_pass1, cudaFuncAttributeMaxDynamicSharedMemorySize, SMEM_BYTES);
    msa_pass1<<<B_ROWS / ROWS, 256, SMEM_BYTES>>>(amp, pitch, bnd, decay, weights, out);
}

// round 17
// speedup vs baseline: 1.1862x; 1.1862x over previous
#include <cuda_runtime.h>
#include <cstdint>
#include <cstddef>

// Problem shape (fixed for this registry entry)
#define B_ROWS 4096
#define T_LEN  8192
#define K_WIN  5

// ---- tiling: WTILE=128 (measured-best), single in-place ring, 4 slots ----
#define ROWS   32                 // rows per block (one lane per row in LIF/combiner warps)
#define WTILE  128                // timesteps per tile
#define SLOTS  4                  // ring depth (x overwritten by spike masks in place)
#define NTILES (T_LEN / WTILE)    // 64
#define GPR    (WTILE / 4)        // 32 float4 per row-tile
#define RSTR   33                 // padded row stride (f4): conflict-free LDS.128

#define X_F4   (SLOTS * 3 * ROWS * RSTR)    // 12672 f4 = 202.7 KB
#define SMEM_BYTES (X_F4 * 16)

// Normalization speculation: sal values are exact integers in {0,1,2,3}; rows
// almost surely reach max=3 (verified R9-R16: fixup is a universal fast-path exit).
#define INV3 (1.0f / 3.000001f)

#define PAR4(i) ((unsigned)((((unsigned)(i)) >> 2) & 1u))

// ---------------- mbarrier helpers ----------------
__device__ __forceinline__ void mbar_init(unsigned addr, unsigned count) {
    asm volatile("mbarrier.init.shared.b64 [%0], %1;" :: "r"(addr), "r"(count) : "memory");
}
__device__ __forceinline__ void mbar_arrive(unsigned addr) {
    asm volatile("mbarrier.arrive.shared.b64 _, [%0];" :: "r"(addr) : "memory");
}
__device__ __forceinline__ void mbar_wait(unsigned addr, unsigned parity) {
    unsigned done;
    asm volatile("{\n\t.reg .pred p;\n\t"
                 "mbarrier.try_wait.parity.acquire.cta.shared::cta.b64 p, [%1], %2;\n\t"
                 "selp.b32 %0, 1, 0, p;\n\t}"
                 : "=r"(done) : "r"(addr), "r"(parity) : "memory");
    if (!done) {
        asm volatile("{\n\t.reg .pred P1;\n\t"
                     "WL_%=:\n\t"
                     "mbarrier.try_wait.parity.acquire.cta.shared::cta.b64 P1, [%0], %1, 0x989680;\n\t"
                     "@P1 bra.uni WD_%=;\n\t"
                     "bra.uni WL_%=;\n\t"
                     "WD_%=:\n\t}"
                     :: "r"(addr), "r"(parity) : "memory");
    }
}
__device__ __forceinline__ void cp_async16(unsigned smem_addr, const void* gptr) {
    asm volatile("cp.async.cg.shared.global [%0], [%1], 16;" :: "r"(smem_addr), "l"(gptr));
}
__device__ __forceinline__ void cp_async_arrive_noinc(unsigned mbar_addr) {
    asm volatile("cp.async.mbarrier.arrive.noinc.shared.b64 [%0];" :: "r"(mbar_addr) : "memory");
}

// ---------------- top-5 streaming insert (strict > preserves lowest-index ties) ----
__device__ __forceinline__ void top5_insert(float s, int t, float tv[5], int ti[5]) {
    if (s > tv[4]) {
        if (s > tv[0]) {
            tv[4]=tv[3]; ti[4]=ti[3]; tv[3]=tv[2]; ti[3]=ti[2];
            tv[2]=tv[1]; ti[2]=ti[1]; tv[1]=tv[0]; ti[1]=ti[0];
            tv[0]=s; ti[0]=t;
        } else if (s > tv[1]) {
            tv[4]=tv[3]; ti[4]=ti[3]; tv[3]=tv[2]; ti[3]=ti[2];
            tv[2]=tv[1]; ti[2]=ti[1]; tv[1]=s; ti[1]=t;
        } else if (s > tv[2]) {
            tv[4]=tv[3]; ti[4]=ti[3]; tv[3]=tv[2]; ti[3]=ti[2];
            tv[2]=s; ti[2]=t;
        } else if (s > tv[3]) {
            tv[4]=tv[3]; ti[4]=ti[3]; tv[3]=s; ti[3]=t;
        } else {
            tv[4]=s; ti[4]=t;
        }
    }
}

// Exact LIF step (R10/R12/R15-verified): FSETP pred-as-data + FSEL.
__device__ __forceinline__ float lif1(float x, float d, float& v) {
    float a = fmaf(d, v, x);
    float u = a - 1.0f;
    bool  p = (a >= 1.0f);
    v = p ? u : a;
    return p ? 1.0f : 0.0f;
}

// =====================================================================================
// Single fused kernel — 8 warps, single 4-slot in-place ring (R15 structure):
//   warp 0 (SMSP0): filler rows 0-15      warp 4 (SMSP0): filler rows 16-31
//   warp 1 (SMSP1): combiner (with saturation early-out)
//   warp 2 (SMSP2): drainer A (rows 0-15) warp 3 (SMSP3): drainer B (rows 16-31)
//   warp 5 (SMSP1): LIF ch0   warp 6 (SMSP2): LIF ch1   warp 7 (SMSP3): LIF ch2
// Ring protocol per slot s:
//   filler: wait sdone[s] (i>=4) -> cp.async x -> arrive full[s]
//   LIF:    wait full[s]         -> read x / overwrite with masks -> arrive cdone[s]
//   comb+drainers: wait cdone[s] -> read masks -> arrive sdone[s]
// Combiner early-out: once tv[4] >= wall (= max possible sal, computed in identical
// fmaf order), no element can change top-5 or max -> skip the scan (exact no-op).
// Epilogue: fused fixup via named barrier 7 (96 threads; measure-zero miss path).
// =====================================================================================
extern "C" __global__ void __launch_bounds__(256, 1)
msa_pass1(const float* __restrict__ amp, const float* __restrict__ pitch,
          const float* __restrict__ bnd, const float* __restrict__ decay,
          const float* __restrict__ weights, float* __restrict__ out)
{
    extern __shared__ float4 smem[];
    float4* smx = smem;            // 4-slot ring: x tiles, overwritten by spike masks
    float*  sfix = reinterpret_cast<float*>(smx);   // 32 floats, safe after all drains
    __shared__ __align__(8) unsigned long long s_mb[12];
    unsigned mb = (unsigned)__cvta_generic_to_shared(s_mb);
    // full[s]: s*8 ; cdone[s]: (4+s)*8 ; sdone[s]: (8+s)*8

    const int tid  = threadIdx.x;
    const int lane = tid & 31;
    const int warp = tid >> 5;
    const int b0   = blockIdx.x * ROWS;

    if (tid == 0) {
        #pragma unroll
        for (int s = 0; s < SLOTS; ++s) {
            mbar_init(mb + (0 + s) * 8, 64);   // full  (2 filler warps x 32)
            mbar_init(mb + (4 + s) * 8, 96);   // cdone (3 LIF warps)
            mbar_init(mb + (8 + s) * 8, 96);   // sdone (combiner + 2 drainers)
        }
        asm volatile("fence.proxy.async.shared::cta;" ::: "memory");
    }
    __syncthreads();

    float* out_sal = out + B_ROWS;

    if (warp == 0 || warp == 4) {
        // ---------------- fillers: lane = 16B chunk (0..31), each covers 16 rows ----
        const int cc = lane;
        const int rbase = (warp == 0) ? 0 : 16;
        for (int i = 0; i < NTILES; ++i) {
            const int s = i & 3;
            if (i >= SLOTS)
                mbar_wait(mb + (8 + s) * 8, PAR4(i - SLOTS));   // slot fully consumed
            #pragma unroll
            for (int c = 0; c < 3; ++c) {
                const float* src = (c == 0) ? amp : (c == 1) ? pitch : bnd;
                float4* dst = smx + (size_t)(s * 3 + c) * ROWS * RSTR;
                #pragma unroll 8
                for (int q = 0; q < 16; ++q) {
                    const int r = rbase + q;
                    unsigned sa = (unsigned)__cvta_generic_to_shared(dst + r * RSTR + cc);
                    cp_async16(sa, src + (size_t)(b0 + r) * T_LEN
                                   + (size_t)i * WTILE + cc * 4);
                }
            }
            cp_async_arrive_noinc(mb + (0 + s) * 8);            // full
        }
    } else if (warp >= 5) {
        // ------- LIF warp, channel c = warp-5: lane = row; in-place mask write -------
        const int c = warp - 5;
        const int r = lane;
        const float d = __ldg(&decay[c]);
        float v = 0.0f;

        for (int i = 0; i < NTILES; ++i) {
            const int s = i & 3;
            mbar_wait(mb + (0 + s) * 8, PAR4(i));               // x ready (ONLY wait)

            float4* X = smx + ((size_t)(s * 3 + c) * ROWS + r) * RSTR;

            float4 nxt = X[0];
            #pragma unroll 8
            for (int g = 0; g < GPR; ++g) {
                const float4 x = nxt;
                if (g + 1 < GPR) nxt = X[g + 1];   // prefetch before overwrite of X[g]
                float4 m;
                m.x = lif1(x.x, d, v);
                m.y = lif1(x.y, d, v);
                m.z = lif1(x.z, d, v);
                m.w = lif1(x.w, d, v);
                X[g] = m;                          // in-place: x slot becomes mask slot
            }
            mbar_arrive(mb + (4 + s) * 8);                      // cdone
        }
    } else if (warp == 1) {
        // ------ combiner: lane = row; max + gated top-5, with saturation early-out ----
        const int r = lane;
        const float w0 = __ldg(&weights[0]), w1 = __ldg(&weights[1]), w2 = __ldg(&weights[2]);
        // Max possible sal, computed in the IDENTICAL fmaf order as sv below
        // (all masks == 1.0f) so the saturation compare is bit-exact.
        const float wall = fmaf(w2, 1.0f, fmaf(w1, 1.0f, w0 * 1.0f));
        float mx = 0.0f;
        float tv[K_WIN] = {-1.0f, -1.0f, -1.0f, -1.0f, -1.0f};
        int   ti[K_WIN] = {0, 0, 0, 0, 0};

        for (int i = 0; i < NTILES; ++i) {
            const int s = i & 3;
            mbar_wait(mb + (4 + s) * 8, PAR4(i));               // masks ready

            // Early-out: top-5 fully saturated at the ceiling -> no element can
            // change tv/ti (strict > insert) or mx. Exact no-op suppression.
            // __all_sync keeps the warp convergent (rows saturate at different times).
            if (!__all_sync(0xffffffffu, tv[4] >= wall)) {
                const float4* S0 = smx + ((size_t)(s * 3 + 0) * ROWS + r) * RSTR;
                const float4* S1 = smx + ((size_t)(s * 3 + 1) * ROWS + r) * RSTR;
                const float4* S2 = smx + ((size_t)(s * 3 + 2) * ROWS + r) * RSTR;

                float tm = -1.0f;
                #pragma unroll 8
                for (int g = 0; g < GPR; ++g) {
                    const float4 m0 = S0[g];
                    const float4 m1 = S1[g];
                    const float4 m2 = S2[g];
                    float4 sv;
                    sv.x = fmaf(w2, m2.x, fmaf(w1, m1.x, w0 * m0.x));
                    sv.y = fmaf(w2, m2.y, fmaf(w1, m1.y, w0 * m0.y));
                    sv.z = fmaf(w2, m2.z, fmaf(w1, m1.z, w0 * m0.z));
                    sv.w = fmaf(w2, m2.w, fmaf(w1, m1.w, w0 * m0.w));
                    tm = fmaxf(tm, fmaxf(fmaxf(sv.x, sv.y), fmaxf(sv.z, sv.w)));
                }
                mx = fmaxf(mx, tm);

                // Gated rescan: only when this tile beats the current 5th value.
                if (tm > tv[4]) {
                    const int tb = i * WTILE;
                    for (int g = 0; g < GPR; ++g) {
                        const float4 m0 = S0[g];
                        const float4 m1 = S1[g];
                        const float4 m2 = S2[g];
                        float4 sv;
                        sv.x = fmaf(w2, m2.x, fmaf(w1, m1.x, w0 * m0.x));
                        sv.y = fmaf(w2, m2.y, fmaf(w1, m1.y, w0 * m0.y));
                        sv.z = fmaf(w2, m2.z, fmaf(w1, m1.z, w0 * m0.z));
                        sv.w = fmaf(w2, m2.w, fmaf(w1, m1.w, w0 * m0.w));
                        const int t = tb + g * 4;
                        top5_insert(sv.x, t + 0, tv, ti);
                        top5_insert(sv.y, t + 1, tv, ti);
                        top5_insert(sv.z, t + 2, tv, ti);
                        top5_insert(sv.w, t + 3, tv, ti);
                    }
                }
            }
            mbar_arrive(mb + (8 + s) * 8);                      // sdone (1 of 3)
        }
        // If we early-outed, mx may lag tv[0]; the true row max is max(mx, tv[0]).
        mx = fmaxf(mx, tv[0]);

        // ---- row tail: mu, topk_idx; publish fix factor for epilogue ----
        const int b = b0 + r;
        const float inv = 1.0f / (mx + 1e-6f);
        const float fix = (mx == 3.0f) ? 1.0f : (3.000001f * inv);
        sfix[r] = fix;     // ring is dead by now
        const float n0 = tv[0]*inv, n1 = tv[1]*inv, n2 = tv[2]*inv,
                    n3 = tv[3]*inv, n4 = tv[4]*inv;
        const float avg = ((((n0 + n1) + n2) + n3) + n4) / 5.0f;
        out[b] = 0.5f + 2.0f * tanhf(1.8f * avg);
        float* out_idx = out + B_ROWS + (size_t)B_ROWS * T_LEN;
        #pragma unroll
        for (int k = 0; k < K_WIN; ++k)
            out_idx[(size_t)b * K_WIN + k] = (float)ti[k];

        // ---- epilogue: meet drainers, rescale own row if needed (measure-zero path) ----
        asm volatile("bar.sync 7, 96;" ::: "memory");
        const float f = sfix[r];
        if (f != 1.0f) {
            float4* row4 = reinterpret_cast<float4*>(out_sal + (size_t)b * T_LEN);
            for (int it = 0; it < T_LEN / 8; ++it) {       // first half of row
                float4 vv = row4[it];
                vv.x *= f; vv.y *= f; vv.z *= f; vv.w *= f;
                row4[it] = vv;
            }
        }
    } else {
        // -------- drainers (warps 2,3): lane = 16B chunk; 16 rows each --------
        const int cc = lane;
        const int rbase = (warp == 2) ? 0 : 16;
        const float w0 = __ldg(&weights[0]), w1 = __ldg(&weights[1]), w2 = __ldg(&weights[2]);
        for (int j = 0; j < NTILES; ++j) {
            const int s = j & 3;
            mbar_wait(mb + (4 + s) * 8, PAR4(j));               // masks ready
            const float4* P0 = smx + (size_t)(s * 3 + 0) * ROWS * RSTR;
            const float4* P1 = smx + (size_t)(s * 3 + 1) * ROWS * RSTR;
            const float4* P2 = smx + (size_t)(s * 3 + 2) * ROWS * RSTR;
            #pragma unroll 4
            for (int q = 0; q < 16; ++q) {
                const int r = rbase + q;
                const float4 m0 = P0[r * RSTR + cc];
                const float4 m1 = P1[r * RSTR + cc];
                const float4 m2 = P2[r * RSTR + cc];
                float4 sv;
                sv.x = fmaf(w2, m2.x, fmaf(w1, m1.x, w0 * m0.x)) * INV3;
                sv.y = fmaf(w2, m2.y, fmaf(w1, m1.y, w0 * m0.y)) * INV3;
                sv.z = fmaf(w2, m2.z, fmaf(w1, m1.z, w0 * m0.z)) * INV3;
                sv.w = fmaf(w2, m2.w, fmaf(w1, m1.w, w0 * m0.w)) * INV3;
                __stcs(reinterpret_cast<float4*>(out_sal + (size_t)(b0 + r) * T_LEN
                                                 + (size_t)j * WTILE + cc * 4), sv);
            }
            mbar_arrive(mb + (8 + s) * 8);                      // sdone (2,3 of 3)
        }

        // ---- epilogue: meet combiner; warp 2 rescales second half of rows if needed ----
        asm volatile("bar.sync 7, 96;" ::: "memory");
        if (warp == 2) {
            const int r = lane;
            const float f = sfix[r];
            if (f != 1.0f) {
                float4* row4 = reinterpret_cast<float4*>(out_sal + (size_t)(b0 + r) * T_LEN);
                for (int it = T_LEN / 8; it < T_LEN / 4; ++it) {   // second half of row
                    float4 vv = row4[it];
                    vv.x *= f; vv.y *= f; vv.z *= f; vv.w *= f;
                    row4[it] = vv;
                }
            }
        }
    }
}

extern "C" void kernel_launch(void* const* d_in, const int* in_sizes, int n_in,
                              void* d_out, int out_size) {
    (void)in_sizes; (void)n_in; (void)out_size;
    const float* amp     = (const float*)d_in[0];
    const float* pitch   = (const float*)d_in[1];
    const float* bnd     = (const float*)d_in[2];
    const float* decay   = (const float*)d_in[3];
    const float* weights = (const float*)d_in[4];
    float* out = (float*)d_out;

    cudaFuncSetAttribute(msa_pass1, cudaFuncAttributeMaxDynamicSharedMemorySize, SMEM_BYTES);
    msa_pass1<<<B_ROWS / ROWS, 256, SMEM_BYTES>>>(amp, pitch, bnd, decay, weights, out);
}